// round 6
// baseline (speedup 1.0000x reference)
#include <cuda_runtime.h>
#include <cuda_bf16.h>
#include <math.h>

typedef unsigned long long ull;

// Problem constants
#define BB   256          // batch
#define TT   512          // seq len
#define HH   256          // hidden
#define GG   1024         // 4*H gates
#define CC   128          // classes
#define MM   (BB*TT)      // 131072 rows for input GEMMs

// ---------------- scratch (device globals; no allocs allowed) ----------------
__device__ float g_GX[(size_t)MM * GG];      // 512 MB  pregates, layout [t][b][gate]
__device__ float g_HBUF[(size_t)MM * HH];    // 128 MB  layer-0 hidden states
__device__ float g_H0[BB * HH];
__device__ float g_H1[BB * HH];

// ---------------- packed f32x2 helpers (Blackwell FFMA2 path) ----------------
__device__ __forceinline__ ull pack2(float x, float y) {
    ull r;
    asm("mov.b64 %0, {%1, %2};" : "=l"(r) : "f"(x), "f"(y));
    return r;
}
__device__ __forceinline__ float2 unpack2(ull v) {
    float2 r;
    asm("mov.b64 {%0, %1}, %2;" : "=f"(r.x), "=f"(r.y) : "l"(v));
    return r;
}
__device__ __forceinline__ ull ffma2x(ull a, ull b, ull c) {
    ull d;
    asm("fma.rn.f32x2 %0, %1, %2, %3;" : "=l"(d) : "l"(a), "l"(b), "l"(c));
    return d;
}

// fast activations (error ~1e-6, well inside 1e-3 budget)
__device__ __forceinline__ float fsigm(float x) {
    float e = __expf(-x);
    return __fdividef(1.0f, 1.0f + e);
}
__device__ __forceinline__ float ftanh(float x) {
    float e = __expf(2.0f * x);           // overflow -> inf -> result 1 (correct)
    return 1.0f - __fdividef(2.0f, e + 1.0f);
}

#define CLUSTER_ARRIVE() asm volatile("barrier.cluster.arrive.aligned;" ::: "memory")
#define CLUSTER_WAIT()   asm volatile("barrier.cluster.wait.aligned;"   ::: "memory")

// ---------------- big GEMM:  GX[t][b][n] = sum_k A[m,k]*W[n,k] + b1[n] + b2[n]
// A: [MM,256] row-major (x, or g_HBUF), m = b*TT + t. W: [1024,256] row-major.
// Tiles: BM=128, BN=64, BK=16, 256 threads, thread tile 8x4 (4 m-pairs x 4 n).
__global__ void __launch_bounds__(256) gemm_gx(const float* __restrict__ Aext,
                                               int useExt,
                                               const float* __restrict__ W,
                                               const float* __restrict__ b1,
                                               const float* __restrict__ b2) {
    __shared__ __align__(16) float As[16][128];
    __shared__ __align__(16) float Bs[16][64];

    const float* __restrict__ A = useExt ? Aext : g_HBUF;
    float* __restrict__ Cout = g_GX;

    const int tid = threadIdx.x;
    const int ty = tid >> 4;          // 0..15  (m group of 8)
    const int tx = tid & 15;          // 0..15  (n group of 4)
    const int bm0 = blockIdx.y * 128;
    const int bn0 = blockIdx.x * 64;

    ull acc[4][4];
    #pragma unroll
    for (int i = 0; i < 4; i++)
        #pragma unroll
        for (int j = 0; j < 4; j++) acc[i][j] = 0ull;

    for (int k0 = 0; k0 < 256; k0 += 16) {
        #pragma unroll
        for (int i = 0; i < 2; i++) {
            int s = tid + i * 256;          // 0..511
            int row = s >> 2;               // 0..127
            int kg = (s & 3) * 4;           // 0,4,8,12
            float4 v = *(const float4*)&A[(size_t)(bm0 + row) * 256 + k0 + kg];
            As[kg + 0][row] = v.x; As[kg + 1][row] = v.y;
            As[kg + 2][row] = v.z; As[kg + 3][row] = v.w;
        }
        {
            int row = tid >> 2;             // 0..63
            int kg = (tid & 3) * 4;
            float4 v = *(const float4*)&W[(size_t)(bn0 + row) * 256 + k0 + kg];
            Bs[kg + 0][row] = v.x; Bs[kg + 1][row] = v.y;
            Bs[kg + 2][row] = v.z; Bs[kg + 3][row] = v.w;
        }
        __syncthreads();
        #pragma unroll
        for (int k = 0; k < 16; k++) {
            const ull* ap = (const ull*)&As[k][ty * 8];
            ull a0 = ap[0], a1 = ap[1], a2 = ap[2], a3 = ap[3];
            float4 bv = *(const float4*)&Bs[k][tx * 4];
            ull bb0 = pack2(bv.x, bv.x);
            ull bb1 = pack2(bv.y, bv.y);
            ull bb2 = pack2(bv.z, bv.z);
            ull bb3 = pack2(bv.w, bv.w);
            acc[0][0] = ffma2x(a0, bb0, acc[0][0]);
            acc[1][0] = ffma2x(a1, bb0, acc[1][0]);
            acc[2][0] = ffma2x(a2, bb0, acc[2][0]);
            acc[3][0] = ffma2x(a3, bb0, acc[3][0]);
            acc[0][1] = ffma2x(a0, bb1, acc[0][1]);
            acc[1][1] = ffma2x(a1, bb1, acc[1][1]);
            acc[2][1] = ffma2x(a2, bb1, acc[2][1]);
            acc[3][1] = ffma2x(a3, bb1, acc[3][1]);
            acc[0][2] = ffma2x(a0, bb2, acc[0][2]);
            acc[1][2] = ffma2x(a1, bb2, acc[1][2]);
            acc[2][2] = ffma2x(a2, bb2, acc[2][2]);
            acc[3][2] = ffma2x(a3, bb2, acc[3][2]);
            acc[0][3] = ffma2x(a0, bb3, acc[0][3]);
            acc[1][3] = ffma2x(a1, bb3, acc[1][3]);
            acc[2][3] = ffma2x(a2, bb3, acc[2][3]);
            acc[3][3] = ffma2x(a3, bb3, acc[3][3]);
        }
        __syncthreads();
    }

    float4 b1v = *(const float4*)&b1[bn0 + tx * 4];
    float4 b2v = *(const float4*)&b2[bn0 + tx * 4];
    float4 bias = make_float4(b1v.x + b2v.x, b1v.y + b2v.y,
                              b1v.z + b2v.z, b1v.w + b2v.w);
    #pragma unroll
    for (int i = 0; i < 4; i++) {
        float2 q0 = unpack2(acc[i][0]);
        float2 q1 = unpack2(acc[i][1]);
        float2 q2 = unpack2(acc[i][2]);
        float2 q3 = unpack2(acc[i][3]);
        size_t m0 = (size_t)(bm0 + ty * 8 + 2 * i);
        size_t m1 = m0 + 1;
        // permuted output: row = t*BB + b, with m = b*TT + t
        size_t r0 = (m0 & (TT - 1)) * BB + (m0 >> 9);
        size_t r1 = (m1 & (TT - 1)) * BB + (m1 >> 9);
        float4 v0 = make_float4(q0.x + bias.x, q1.x + bias.y, q2.x + bias.z, q3.x + bias.w);
        float4 v1 = make_float4(q0.y + bias.x, q1.y + bias.y, q2.y + bias.z, q3.y + bias.w);
        *(float4*)&Cout[r0 * GG + bn0 + tx * 4] = v0;
        *(float4*)&Cout[r1 * GG + bn0 + tx * 4] = v1;
    }
}

// ---------------- persistent recurrence kernel -------------------------------
// Grid (8, 16): x = hcol group (32 cols), y = batch-row group (16 rows).
// Cluster (8,1,1): the 8 CTAs sharing a row group — the only CTAs whose h
// outputs we consume — sync via barrier.cluster (~0.2us) instead of a global
// atomic barrier. whh slice (128 gate-rows x 256 k = 128KB) in SMEM for the
// whole sequence; c in registers; h double-buffered in global (L2).
__global__ void __launch_bounds__(128, 1) lstm_persist(const float* __restrict__ whh,
                                                       int writeHbuf) {
    extern __shared__ float sm[];
    float* sWs = sm;              // [256][128]  weights transposed [k][bh*4+g]
    float* sAs = sm + 256 * 128;  // [256][16]   h tile transposed [k][row]

    const int tid  = threadIdx.x;
    const int w    = tid >> 5;
    const int lane = tid & 31;
    const int hcol = ((w & 1) << 4) | (lane & 15);   // 0..31 (16 distinct/warp)
    const int rq   = ((w >> 1) << 1) | (lane >> 4);  // 0..3
    const int c0   = blockIdx.x * 32;                // h-col group
    const int bm   = blockIdx.y * 16;                // batch-row group
    const int col  = c0 + hcol;

    // one-time weight stage: 128 gate-rows (bh*4+g) x 256 k
    for (int i = tid; i < 128 * 64; i += 128) {
        int lr = i >> 6;              // 0..127 local row
        int kk = (i & 63) << 2;       // k0
        int bh = lr >> 2, g = lr & 3;
        float4 v = *(const float4*)&whh[(size_t)(g * HH + c0 + bh) * HH + kk];
        sWs[(kk + 0) * 128 + lr] = v.x;
        sWs[(kk + 1) * 128 + lr] = v.y;
        sWs[(kk + 2) * 128 + lr] = v.z;
        sWs[(kk + 3) * 128 + lr] = v.w;
    }
    __syncthreads();

    float creg[4] = {0.f, 0.f, 0.f, 0.f};
    int rows[4];
    #pragma unroll
    for (int r = 0; r < 4; r++) rows[r] = bm + rq * 4 + r;

    // initial pregate prefetch for t=0
    float pg_i[4], pg_f[4], pg_g[4], pg_o[4];
    #pragma unroll
    for (int r = 0; r < 4; r++) {
        size_t base = (size_t)rows[r] * GG + col;     // t=0
        pg_i[r] = g_GX[base];
        pg_f[r] = g_GX[base + 256];
        pg_g[r] = g_GX[base + 512];
        pg_o[r] = g_GX[base + 768];
    }

    for (int t = 0; t < TT; t++) {
        const float* __restrict__ hin  = (t & 1) ? g_H1 : g_H0;
        float* __restrict__       hout = (t & 1) ? g_H0 : g_H1;

        ull ai0 = 0, ai1 = 0, af0 = 0, af1 = 0;
        ull ag0 = 0, ag1 = 0, ao0 = 0, ao1 = 0;

        if (t > 0) {   // h == 0 at t=0, recurrent term vanishes
            // stage hin tile (16 rows x 256 k), transposed [k][row]
            {
                int r  = tid & 15;
                int kc = tid >> 4;                     // 0..7, 32 k each
                const float* hrow = &hin[(bm + r) * HH + kc * 32];
                #pragma unroll
                for (int j = 0; j < 8; j++) {
                    float4 v = *(const float4*)&hrow[j * 4];
                    int k0 = kc * 32 + j * 4;
                    sAs[(k0 + 0) * 16 + r] = v.x;
                    sAs[(k0 + 1) * 16 + r] = v.y;
                    sAs[(k0 + 2) * 16 + r] = v.z;
                    sAs[(k0 + 3) * 16 + r] = v.w;
                }
            }
            __syncthreads();

            const float* ap = &sAs[rq * 4];
            const float* bp = &sWs[hcol * 4];
            #pragma unroll 8
            for (int k = 0; k < 256; k++) {
                ull a0 = *(const ull*)(ap + k * 16);
                ull a1 = *(const ull*)(ap + k * 16 + 2);
                float4 bv = *(const float4*)(bp + k * 128);   // (i,f,g,o)
                ull bi = pack2(bv.x, bv.x);
                ull bf = pack2(bv.y, bv.y);
                ull bg = pack2(bv.z, bv.z);
                ull bo = pack2(bv.w, bv.w);
                ai0 = ffma2x(a0, bi, ai0); ai1 = ffma2x(a1, bi, ai1);
                af0 = ffma2x(a0, bf, af0); af1 = ffma2x(a1, bf, af1);
                ag0 = ffma2x(a0, bg, ag0); ag1 = ffma2x(a1, bg, ag1);
                ao0 = ffma2x(a0, bo, ao0); ao1 = ffma2x(a1, bo, ao1);
            }
            __syncthreads();   // sAs re-staged next step
        }

        float iv[4], fv[4], gv[4], ov[4];
        {
            float2 p;
            p = unpack2(ai0); iv[0] = p.x; iv[1] = p.y;
            p = unpack2(ai1); iv[2] = p.x; iv[3] = p.y;
            p = unpack2(af0); fv[0] = p.x; fv[1] = p.y;
            p = unpack2(af1); fv[2] = p.x; fv[3] = p.y;
            p = unpack2(ag0); gv[0] = p.x; gv[1] = p.y;
            p = unpack2(ag1); gv[2] = p.x; gv[3] = p.y;
            p = unpack2(ao0); ov[0] = p.x; ov[1] = p.y;
            p = unpack2(ao1); ov[2] = p.x; ov[3] = p.y;
        }

        #pragma unroll
        for (int r = 0; r < 4; r++) {
            float si = fsigm(iv[r] + pg_i[r]);
            float sf = fsigm(fv[r] + pg_f[r]);
            float tg = ftanh(gv[r] + pg_g[r]);
            float so = fsigm(ov[r] + pg_o[r]);
            float c  = sf * creg[r] + si * tg;
            creg[r]  = c;
            float h  = so * ftanh(c);
            hout[rows[r] * HH + col] = h;
            if (writeHbuf)
                g_HBUF[((size_t)rows[r] * TT + t) * HH + col] = h;
        }

        if (t < TT - 1) {
            CLUSTER_ARRIVE();          // release: h stores visible to cluster
            // prefetch next step's pregates while peers catch up
            #pragma unroll
            for (int r = 0; r < 4; r++) {
                size_t base = ((size_t)(t + 1) * BB + rows[r]) * GG + col;
                pg_i[r] = g_GX[base];
                pg_f[r] = g_GX[base + 256];
                pg_g[r] = g_GX[base + 512];
                pg_o[r] = g_GX[base + 768];
            }
            CLUSTER_WAIT();            // acquire
        }
    }
}

// ---------------- FC + log_softmax ------------------------------------------
__global__ void __launch_bounds__(128) fc_kernel(const float* __restrict__ wfc,
                                                 const float* __restrict__ bfc,
                                                 float* __restrict__ out) {
    const int b = blockIdx.x;
    const int tid = threadIdx.x;  // 128 = one class per thread
    __shared__ float h[256];
    h[tid] = g_H0[b * HH + tid];
    h[tid + 128] = g_H0[b * HH + tid + 128];
    __syncthreads();

    float acc = bfc[tid];
    const float* wp = wfc + (size_t)tid * HH;
    #pragma unroll 8
    for (int k = 0; k < 256; k++) acc += h[k] * wp[k];

    float m = acc;
    #pragma unroll
    for (int o = 16; o > 0; o >>= 1)
        m = fmaxf(m, __shfl_xor_sync(0xffffffffu, m, o));
    __shared__ float smax[4], ssum[4];
    int wid = tid >> 5, lane = tid & 31;
    if (lane == 0) smax[wid] = m;
    __syncthreads();
    m = fmaxf(fmaxf(smax[0], smax[1]), fmaxf(smax[2], smax[3]));

    float e = expf(acc - m);
    float s = e;
    #pragma unroll
    for (int o = 16; o > 0; o >>= 1)
        s += __shfl_xor_sync(0xffffffffu, s, o);
    if (lane == 0) ssum[wid] = s;
    __syncthreads();
    s = ssum[0] + ssum[1] + ssum[2] + ssum[3];

    out[b * CC + tid] = acc - m - logf(s);
}

// ---------------- launch ------------------------------------------------------
extern "C" void kernel_launch(void* const* d_in, const int* in_sizes, int n_in,
                              void* d_out, int out_size) {
    const float* x    = (const float*)d_in[0];
    const float* wih0 = (const float*)d_in[1];
    const float* whh0 = (const float*)d_in[2];
    const float* bih0 = (const float*)d_in[3];
    const float* bhh0 = (const float*)d_in[4];
    const float* wih1 = (const float*)d_in[5];
    const float* whh1 = (const float*)d_in[6];
    const float* bih1 = (const float*)d_in[7];
    const float* bhh1 = (const float*)d_in[8];
    const float* wfc  = (const float*)d_in[9];
    const float* bfc  = (const float*)d_in[10];
    float* out = (float*)d_out;

    const int persist_smem = (256 * 128 + 256 * 16) * (int)sizeof(float); // 144 KB
    cudaFuncSetAttribute(lstm_persist,
                         cudaFuncAttributeMaxDynamicSharedMemorySize,
                         persist_smem);

    dim3 gemm_grid(16, 1024);   // N/64, M/128

    cudaLaunchConfig_t cfg = {};
    cfg.gridDim = dim3(8, 16, 1);      // col-groups x row-groups
    cfg.blockDim = dim3(128, 1, 1);
    cfg.dynamicSmemBytes = persist_smem;
    cudaLaunchAttribute attrs[1];
    attrs[0].id = cudaLaunchAttributeClusterDimension;
    attrs[0].val.clusterDim = {8, 1, 1};  // the 8 CTAs sharing a row group
    cfg.attrs = attrs;
    cfg.numAttrs = 1;

    // Layer 0
    gemm_gx<<<gemm_grid, 256>>>(x, 1, wih0, bih0, bhh0);
    cudaLaunchKernelEx(&cfg, lstm_persist, whh0, 1);

    // Layer 1
    gemm_gx<<<gemm_grid, 256>>>(nullptr, 0, wih1, bih1, bhh1);
    cudaLaunchKernelEx(&cfg, lstm_persist, whh1, 0);

    // Head
    fc_kernel<<<256, 128>>>(wfc, bfc, out);
}

// round 7
// speedup vs baseline: 1.2523x; 1.2523x over previous
#include <cuda_runtime.h>
#include <cuda_bf16.h>
#include <math.h>

typedef unsigned long long ull;

// Problem constants
#define BB   256          // batch
#define TT   512          // seq len
#define HH   256          // hidden
#define GG   1024         // 4*H gates
#define CC   128          // classes
#define MM   (BB*TT)      // 131072 rows for input GEMMs

// ---------------- scratch (device globals; no allocs allowed) ----------------
__device__ float g_GX[(size_t)MM * GG];      // 512 MB  pregates, layout [t][b][gate]
__device__ float g_HBUF[(size_t)MM * HH];    // 128 MB  layer-0 hidden states
__device__ float g_H0[BB * HH];
__device__ float g_H1[BB * HH];
__device__ unsigned int g_bar;               // grid barrier counter

// ---------------- packed f32x2 helpers (Blackwell FFMA2 path) ----------------
__device__ __forceinline__ ull pack2(float x, float y) {
    ull r;
    asm("mov.b64 %0, {%1, %2};" : "=l"(r) : "f"(x), "f"(y));
    return r;
}
__device__ __forceinline__ float2 unpack2(ull v) {
    float2 r;
    asm("mov.b64 {%0, %1}, %2;" : "=f"(r.x), "=f"(r.y) : "l"(v));
    return r;
}
__device__ __forceinline__ ull ffma2x(ull a, ull b, ull c) {
    ull d;
    asm("fma.rn.f32x2 %0, %1, %2, %3;" : "=l"(d) : "l"(a), "l"(b), "l"(c));
    return d;
}

// fast activations (error ~1e-6, well inside 1e-3 budget)
__device__ __forceinline__ float fsigm(float x) {
    float e = __expf(-x);
    return __fdividef(1.0f, 1.0f + e);
}
__device__ __forceinline__ float ftanh(float x) {
    float e = __expf(2.0f * x);           // overflow -> inf -> result 1 (correct)
    return 1.0f - __fdividef(2.0f, e + 1.0f);
}

// ---------------- big GEMM:  GX[t][b][n] = sum_k A[m,k]*W[n,k] + b1[n] + b2[n]
// A: [MM,256] row-major (x, or g_HBUF), m = b*TT + t. W: [1024,256] row-major.
// Tiles: BM=128, BN=64, BK=16, 256 threads, thread tile 8x4 (4 m-pairs x 4 n).
__global__ void __launch_bounds__(256) gemm_gx(const float* __restrict__ Aext,
                                               int useExt,
                                               const float* __restrict__ W,
                                               const float* __restrict__ b1,
                                               const float* __restrict__ b2) {
    __shared__ __align__(16) float As[16][128];
    __shared__ __align__(16) float Bs[16][64];

    const float* __restrict__ A = useExt ? Aext : g_HBUF;
    float* __restrict__ Cout = g_GX;

    const int tid = threadIdx.x;
    const int ty = tid >> 4;          // 0..15  (m group of 8)
    const int tx = tid & 15;          // 0..15  (n group of 4)
    const int bm0 = blockIdx.y * 128;
    const int bn0 = blockIdx.x * 64;

    ull acc[4][4];
    #pragma unroll
    for (int i = 0; i < 4; i++)
        #pragma unroll
        for (int j = 0; j < 4; j++) acc[i][j] = 0ull;

    for (int k0 = 0; k0 < 256; k0 += 16) {
        #pragma unroll
        for (int i = 0; i < 2; i++) {
            int s = tid + i * 256;          // 0..511
            int row = s >> 2;               // 0..127
            int kg = (s & 3) * 4;           // 0,4,8,12
            float4 v = *(const float4*)&A[(size_t)(bm0 + row) * 256 + k0 + kg];
            As[kg + 0][row] = v.x; As[kg + 1][row] = v.y;
            As[kg + 2][row] = v.z; As[kg + 3][row] = v.w;
        }
        {
            int row = tid >> 2;             // 0..63
            int kg = (tid & 3) * 4;
            float4 v = *(const float4*)&W[(size_t)(bn0 + row) * 256 + k0 + kg];
            Bs[kg + 0][row] = v.x; Bs[kg + 1][row] = v.y;
            Bs[kg + 2][row] = v.z; Bs[kg + 3][row] = v.w;
        }
        __syncthreads();
        #pragma unroll
        for (int k = 0; k < 16; k++) {
            const ull* ap = (const ull*)&As[k][ty * 8];
            ull a0 = ap[0], a1 = ap[1], a2 = ap[2], a3 = ap[3];
            float4 bv = *(const float4*)&Bs[k][tx * 4];
            ull bb0 = pack2(bv.x, bv.x);
            ull bb1 = pack2(bv.y, bv.y);
            ull bb2 = pack2(bv.z, bv.z);
            ull bb3 = pack2(bv.w, bv.w);
            acc[0][0] = ffma2x(a0, bb0, acc[0][0]);
            acc[1][0] = ffma2x(a1, bb0, acc[1][0]);
            acc[2][0] = ffma2x(a2, bb0, acc[2][0]);
            acc[3][0] = ffma2x(a3, bb0, acc[3][0]);
            acc[0][1] = ffma2x(a0, bb1, acc[0][1]);
            acc[1][1] = ffma2x(a1, bb1, acc[1][1]);
            acc[2][1] = ffma2x(a2, bb1, acc[2][1]);
            acc[3][1] = ffma2x(a3, bb1, acc[3][1]);
            acc[0][2] = ffma2x(a0, bb2, acc[0][2]);
            acc[1][2] = ffma2x(a1, bb2, acc[1][2]);
            acc[2][2] = ffma2x(a2, bb2, acc[2][2]);
            acc[3][2] = ffma2x(a3, bb2, acc[3][2]);
            acc[0][3] = ffma2x(a0, bb3, acc[0][3]);
            acc[1][3] = ffma2x(a1, bb3, acc[1][3]);
            acc[2][3] = ffma2x(a2, bb3, acc[2][3]);
            acc[3][3] = ffma2x(a3, bb3, acc[3][3]);
        }
        __syncthreads();
    }

    float4 b1v = *(const float4*)&b1[bn0 + tx * 4];
    float4 b2v = *(const float4*)&b2[bn0 + tx * 4];
    float4 bias = make_float4(b1v.x + b2v.x, b1v.y + b2v.y,
                              b1v.z + b2v.z, b1v.w + b2v.w);
    #pragma unroll
    for (int i = 0; i < 4; i++) {
        float2 q0 = unpack2(acc[i][0]);
        float2 q1 = unpack2(acc[i][1]);
        float2 q2 = unpack2(acc[i][2]);
        float2 q3 = unpack2(acc[i][3]);
        size_t m0 = (size_t)(bm0 + ty * 8 + 2 * i);
        size_t m1 = m0 + 1;
        // permuted output: row = t*BB + b, with m = b*TT + t
        size_t r0 = (m0 & (TT - 1)) * BB + (m0 >> 9);
        size_t r1 = (m1 & (TT - 1)) * BB + (m1 >> 9);
        float4 v0 = make_float4(q0.x + bias.x, q1.x + bias.y, q2.x + bias.z, q3.x + bias.w);
        float4 v1 = make_float4(q0.y + bias.x, q1.y + bias.y, q2.y + bias.z, q3.y + bias.w);
        *(float4*)&Cout[r0 * GG + bn0 + tx * 4] = v0;
        *(float4*)&Cout[r1 * GG + bn0 + tx * 4] = v1;
    }
}

// ---------------- barrier reset ----------------
__global__ void reset_bar() { g_bar = 0u; }

// ---------------- persistent recurrence kernel -------------------------------
// Grid (8,16) = 128 CTAs, 256 threads (8 warps -> 2/SMSP for latency hiding).
// CTA tile: 16 batch rows x 32 h-cols. Thread: 2 rows x 1 col x 4 gates,
// gates accumulated as f32x2 pairs (i,f) and (g,o).
// smem: weights [k][col][4 gates] (128KB, staged once) + h duplicated
// [k][(h,h) per row] (32KB, restaged per step; broadcast LDS for free).
// Inner loop: 2 LDS.128 + 4 FFMA2 per k -> fma-throughput-bound.
__global__ void __launch_bounds__(256, 1) lstm_persist(const float* __restrict__ whh,
                                                       int writeHbuf) {
    extern __shared__ float sm[];
    float* sW = sm;               // [256][128]  sW[k*128 + cl*4 + gate]
    float* sH = sm + 256 * 128;   // [256][32]   sH[k*32 + r*2 + {0,1}] dup

    const int tid  = threadIdx.x;
    const int w    = tid >> 5;            // warp 0..7
    const int lane = tid & 31;
    const int c0   = blockIdx.x * 32;     // h-col group
    const int bm   = blockIdx.y * 16;     // batch-row group
    const int col  = c0 + lane;
    const int r0   = bm + 2 * w;
    const int r1   = r0 + 1;

    // one-time weight stage: 128 local rows (cl*4+g) x 256 k, transposed
    for (int i = tid; i < 128 * 64; i += 256) {
        int lr = i >> 6;              // 0..127 = cl*4 + g
        int kk = (i & 63) << 2;       // k0
        int cl = lr >> 2, g = lr & 3;
        float4 v = *(const float4*)&whh[(size_t)(g * HH + c0 + cl) * HH + kk];
        sW[(kk + 0) * 128 + lr] = v.x;
        sW[(kk + 1) * 128 + lr] = v.y;
        sW[(kk + 2) * 128 + lr] = v.z;
        sW[(kk + 3) * 128 + lr] = v.w;
    }
    __syncthreads();

    float c0reg = 0.f, c1reg = 0.f;

    // t=0 pregate prefetch
    float pi0, pf0, pgg0, po0, pi1, pf1, pgg1, po1;
    {
        size_t b0 = (size_t)r0 * GG + col;
        size_t b1 = (size_t)r1 * GG + col;
        pi0 = g_GX[b0];       pf0 = g_GX[b0 + 256];
        pgg0 = g_GX[b0 + 512]; po0 = g_GX[b0 + 768];
        pi1 = g_GX[b1];       pf1 = g_GX[b1 + 256];
        pgg1 = g_GX[b1 + 512]; po1 = g_GX[b1 + 768];
    }

    const int sr = tid & 15;          // staging row
    const int skc = tid >> 4;         // staging k-chunk 0..15 (16 k each)

    for (int t = 0; t < TT; t++) {
        const float* __restrict__ hin  = (t & 1) ? g_H1 : g_H0;
        float* __restrict__       hout = (t & 1) ? g_H0 : g_H1;

        ull aif0 = 0, ago0 = 0, aif1 = 0, ago1 = 0;

        if (t > 0) {   // h == 0 at t=0, recurrent term vanishes
            // stage hin (16 rows x 256 k) into duplicated smem
            {
                const float* hrow = &hin[(bm + sr) * HH + skc * 16];
                ull* sHu = (ull*)sH;
                #pragma unroll
                for (int j = 0; j < 4; j++) {
                    float4 v = *(const float4*)&hrow[j * 4];
                    int k0 = skc * 16 + j * 4;
                    sHu[(k0 + 0) * 16 + sr] = pack2(v.x, v.x);
                    sHu[(k0 + 1) * 16 + sr] = pack2(v.y, v.y);
                    sHu[(k0 + 2) * 16 + sr] = pack2(v.z, v.z);
                    sHu[(k0 + 3) * 16 + sr] = pack2(v.w, v.w);
                }
            }
            __syncthreads();

            const ulonglong2* hp = (const ulonglong2*)(sH + w * 4);    // +k*32 floats
            const ulonglong2* wp = (const ulonglong2*)(sW + lane * 4); // +k*128 floats
            #pragma unroll 8
            for (int k = 0; k < 256; k++) {
                ulonglong2 hv = hp[(size_t)k * 8];    // (h0,h0),(h1,h1) broadcast
                ulonglong2 wv = wp[(size_t)k * 32];   // (wi,wf),(wg,wo)
                aif0 = ffma2x(hv.x, wv.x, aif0);
                ago0 = ffma2x(hv.x, wv.y, ago0);
                aif1 = ffma2x(hv.y, wv.x, aif1);
                ago1 = ffma2x(hv.y, wv.y, ago1);
            }
            __syncthreads();   // sH re-staged next step
        }

        float2 if0 = unpack2(aif0), go0 = unpack2(ago0);
        float2 if1 = unpack2(aif1), go1 = unpack2(ago1);

        {
            float si = fsigm(if0.x + pi0);
            float sf = fsigm(if0.y + pf0);
            float tg = ftanh(go0.x + pgg0);
            float so = fsigm(go0.y + po0);
            c0reg = sf * c0reg + si * tg;
            float h = so * ftanh(c0reg);
            hout[r0 * HH + col] = h;
            if (writeHbuf) g_HBUF[((size_t)r0 * TT + t) * HH + col] = h;
        }
        {
            float si = fsigm(if1.x + pi1);
            float sf = fsigm(if1.y + pf1);
            float tg = ftanh(go1.x + pgg1);
            float so = fsigm(go1.y + po1);
            c1reg = sf * c1reg + si * tg;
            float h = so * ftanh(c1reg);
            hout[r1 * HH + col] = h;
            if (writeHbuf) g_HBUF[((size_t)r1 * TT + t) * HH + col] = h;
        }

        if (t < TT - 1) {
            __syncthreads();                       // all h stores issued
            if (tid == 0) {
                __threadfence();                   // release h to GPU scope
                atomicAdd(&g_bar, 1u);
            }
            // prefetch next step's pregates while peers arrive
            {
                size_t b0 = ((size_t)(t + 1) * BB + r0) * GG + col;
                size_t b1 = ((size_t)(t + 1) * BB + r1) * GG + col;
                pi0 = g_GX[b0];        pf0 = g_GX[b0 + 256];
                pgg0 = g_GX[b0 + 512]; po0 = g_GX[b0 + 768];
                pi1 = g_GX[b1];        pf1 = g_GX[b1 + 256];
                pgg1 = g_GX[b1 + 512]; po1 = g_GX[b1 + 768];
            }
            if (tid == 0) {
                unsigned target = (unsigned)(t + 1) * 128u;
                unsigned v;
                do {
                    asm volatile("ld.global.acquire.gpu.u32 %0, [%1];"
                                 : "=r"(v) : "l"(&g_bar));
                } while (v < target);
            }
            __syncthreads();
        }
    }
}

// ---------------- FC + log_softmax ------------------------------------------
__global__ void __launch_bounds__(128) fc_kernel(const float* __restrict__ wfc,
                                                 const float* __restrict__ bfc,
                                                 float* __restrict__ out) {
    const int b = blockIdx.x;
    const int tid = threadIdx.x;  // 128 = one class per thread
    __shared__ float h[256];
    h[tid] = g_H0[b * HH + tid];          // TT even -> final h in g_H0? no:
    // t = TT-1 = 511 (odd) -> hout = g_H0. Correct.
    h[tid + 128] = g_H0[b * HH + tid + 128];
    __syncthreads();

    float acc = bfc[tid];
    const float* wp = wfc + (size_t)tid * HH;
    #pragma unroll 8
    for (int k = 0; k < 256; k++) acc += h[k] * wp[k];

    float m = acc;
    #pragma unroll
    for (int o = 16; o > 0; o >>= 1)
        m = fmaxf(m, __shfl_xor_sync(0xffffffffu, m, o));
    __shared__ float smax[4], ssum[4];
    int wid = tid >> 5, lane = tid & 31;
    if (lane == 0) smax[wid] = m;
    __syncthreads();
    m = fmaxf(fmaxf(smax[0], smax[1]), fmaxf(smax[2], smax[3]));

    float e = expf(acc - m);
    float s = e;
    #pragma unroll
    for (int o = 16; o > 0; o >>= 1)
        s += __shfl_xor_sync(0xffffffffu, s, o);
    if (lane == 0) ssum[wid] = s;
    __syncthreads();
    s = ssum[0] + ssum[1] + ssum[2] + ssum[3];

    out[b * CC + tid] = acc - m - logf(s);
}

// ---------------- launch ------------------------------------------------------
extern "C" void kernel_launch(void* const* d_in, const int* in_sizes, int n_in,
                              void* d_out, int out_size) {
    const float* x    = (const float*)d_in[0];
    const float* wih0 = (const float*)d_in[1];
    const float* whh0 = (const float*)d_in[2];
    const float* bih0 = (const float*)d_in[3];
    const float* bhh0 = (const float*)d_in[4];
    const float* wih1 = (const float*)d_in[5];
    const float* whh1 = (const float*)d_in[6];
    const float* bih1 = (const float*)d_in[7];
    const float* bhh1 = (const float*)d_in[8];
    const float* wfc  = (const float*)d_in[9];
    const float* bfc  = (const float*)d_in[10];
    float* out = (float*)d_out;

    const int persist_smem = (256 * 128 + 256 * 32) * (int)sizeof(float); // 160 KB
    cudaFuncSetAttribute(lstm_persist,
                         cudaFuncAttributeMaxDynamicSharedMemorySize,
                         persist_smem);

    dim3 gemm_grid(16, 1024);   // N/64, M/128
    dim3 step_grid(8, 16);      // col-groups x row-groups = 128 CTAs

    // Layer 0
    gemm_gx<<<gemm_grid, 256>>>(x, 1, wih0, bih0, bhh0);
    reset_bar<<<1, 1>>>();
    lstm_persist<<<step_grid, 256, persist_smem>>>(whh0, 1);

    // Layer 1
    gemm_gx<<<gemm_grid, 256>>>(nullptr, 0, wih1, bih1, bhh1);
    reset_bar<<<1, 1>>>();
    lstm_persist<<<step_grid, 256, persist_smem>>>(whh1, 0);

    // Head
    fc_kernel<<<256, 128>>>(wfc, bfc, out);
}